// round 3
// baseline (speedup 1.0000x reference)
#include <cuda_runtime.h>
#include <cuda_bf16.h>
#include <cstdint>
#include <cstddef>

// ---------------- problem sizes ----------------
#define MDIM 8192
#define NDIM 4096
#define KDIM 4096
#define MT 128          // CTA tile M
#define NT 128          // CTA tile N
#define KC 128          // K elements per chunk (int8 -> 128B rows)
#define NCHUNK (KDIM / KC)          // 32
#define STAGES 4
#define A_TILE 16384                // 128 rows x 128B
#define STAGE_BYTES (3 * A_TILE)    // A_hi + A_lo + B = 49152
#define SMEM_BYTES (STAGES * STAGE_BYTES)   // 196608

// ---------------- device scratch (no allocation allowed) ----------------
__device__ __align__(128) int8_t g_A_hi[(size_t)MDIM * KDIM];
__device__ __align__(128) int8_t g_A_lo[(size_t)MDIM * KDIM];
__device__ __align__(128) int8_t g_Wq[(size_t)NDIM * KDIM];
__device__ float g_sA[MDIM];

// ---------------- PTX helpers (base sm_103 target only: no tcgen05) -------
static __device__ __forceinline__ uint32_t smem_u32(const void* p) {
    uint32_t a;
    asm("{ .reg .u64 t; cvta.to.shared.u64 t, %1; cvt.u32.u64 %0, t; }" : "=r"(a) : "l"(p));
    return a;
}

#define CP16(dst, src) \
    asm volatile("cp.async.cg.shared.global [%0], [%1], 16;" :: "r"((uint32_t)(dst)), "l"(src) : "memory")
#define CP_COMMIT() asm volatile("cp.async.commit_group;" ::: "memory")
#define CP_WAIT(n)  asm volatile("cp.async.wait_group %0;" :: "n"(n) : "memory")

#define LDSM4(r0, r1, r2, r3, addr) \
    asm volatile("ldmatrix.sync.aligned.m8n8.x4.shared.b16 {%0,%1,%2,%3}, [%4];" \
                 : "=r"(r0), "=r"(r1), "=r"(r2), "=r"(r3) : "r"(addr))

#define MMA_S8(d, a0, a1, a2, a3, b0, b1) \
    asm volatile("mma.sync.aligned.m16n8k32.row.col.s32.s8.s8.s32 " \
                 "{%0,%1,%2,%3}, {%4,%5,%6,%7}, {%8,%9}, {%0,%1,%2,%3};" \
                 : "+r"((d)[0]), "+r"((d)[1]), "+r"((d)[2]), "+r"((d)[3]) \
                 : "r"(a0), "r"(a1), "r"(a2), "r"(a3), "r"(b0), "r"(b1))

// ---------------- prepass 1: per-row amax + two-level int8 quantization ----
// One block per row of x. s = amax/127, q_hi = rint(x/s), q_lo = rint((x-q_hi*s)*254/s).
__global__ void __launch_bounds__(128) quant_x_kernel(const float* __restrict__ x) {
    const int row = blockIdx.x;
    const int tid = threadIdx.x;
    const float4* __restrict__ xr = (const float4*)(x + (size_t)row * KDIM);
    float4 v[8];
    float am = 0.0f;
    #pragma unroll
    for (int j = 0; j < 8; ++j) {
        v[j] = xr[tid + 128 * j];
        am = fmaxf(am, fmaxf(fmaxf(fabsf(v[j].x), fabsf(v[j].y)),
                             fmaxf(fabsf(v[j].z), fabsf(v[j].w))));
    }
    #pragma unroll
    for (int off = 16; off > 0; off >>= 1)
        am = fmaxf(am, __shfl_xor_sync(0xffffffffu, am, off));
    __shared__ float smax[4];
    if ((tid & 31) == 0) smax[tid >> 5] = am;
    __syncthreads();
    am = fmaxf(fmaxf(smax[0], smax[1]), fmaxf(smax[2], smax[3]));
    am = fmaxf(am, 1e-30f);

    const float s = am * (1.0f / 127.0f);
    const float inv = 127.0f / am;
    const float inv2 = inv * 254.0f;
    if (tid == 0) g_sA[row] = s;

    char4* __restrict__ qh = (char4*)(g_A_hi + (size_t)row * KDIM);
    char4* __restrict__ ql = (char4*)(g_A_lo + (size_t)row * KDIM);
    #pragma unroll
    for (int j = 0; j < 8; ++j) {
        float e[4] = {v[j].x, v[j].y, v[j].z, v[j].w};
        char4 h, l;
        signed char* hp = &h.x;
        signed char* lp = &l.x;
        #pragma unroll
        for (int t = 0; t < 4; ++t) {
            int q = __float2int_rn(e[t] * inv);
            q = max(-127, min(127, q));
            float r = e[t] - (float)q * s;
            int q2 = __float2int_rn(r * inv2);
            q2 = max(-127, min(127, q2));
            hp[t] = (signed char)q;
            lp[t] = (signed char)q2;
        }
        qh[tid + 128 * j] = h;
        ql[tid + 128 * j] = l;
    }
}

// ---------------- prepass 2: int32 weights -> int8 (exact) ----------------
__global__ void __launch_bounds__(256) cvt_w_kernel(const int* __restrict__ w) {
    const size_t n4 = (size_t)NDIM * KDIM / 4;
    const int4* __restrict__ w4 = (const int4*)w;
    char4* __restrict__ dst = (char4*)g_Wq;
    size_t stride = (size_t)gridDim.x * blockDim.x;
    for (size_t i = (size_t)blockIdx.x * blockDim.x + threadIdx.x; i < n4; i += stride) {
        int4 v = w4[i];
        char4 p;
        p.x = (signed char)v.x; p.y = (signed char)v.y;
        p.z = (signed char)v.z; p.w = (signed char)v.w;
        dst[i] = p;
    }
}

// ---------------- main GEMM: mma.sync s8, cp.async 4-stage pipeline --------
// 256 threads = 8 warps, warp tile 32(M) x 64(N), CTA tile 128x128.
// Per K-chunk both A_hi and A_lo MMAs run against the same B fragments.
__global__ void __launch_bounds__(256, 1) qgemm_kernel(
    const float* __restrict__ scale,
    const float* __restrict__ bias,
    float* __restrict__ out
) {
    extern __shared__ char smem[];
    const uint32_t sbase = smem_u32(smem);
    const int tid = threadIdx.x;
    const int m0 = blockIdx.y * MT;
    const int n0 = blockIdx.x * NT;

    const int lane = tid & 31;
    const int wid = tid >> 5;
    const int wm = wid & 3;      // 4 M-groups of 32 rows
    const int wn = wid >> 2;     // 2 N-groups of 64 cols

    // ---- per-thread gmem pointers for cp.async (granule = 16B) ----
    // granule g in a 128x128B tile: row = g>>3, col16 = g&7. thread covers g = tid + i*256.
    const int8_t* pAh = g_A_hi + (size_t)m0 * KDIM;
    const int8_t* pAl = g_A_lo + (size_t)m0 * KDIM;
    const int8_t* pB  = g_Wq  + (size_t)n0 * KDIM;

    // ---- per-thread ldmatrix address components ----
    // A: row within warp M-block, SW128 xor mask constant per thread.
    const int rA = 32 * wm + (lane & 7) + ((lane >> 3) & 1) * 8;
    const int kaddA = ((lane >> 4) & 1) * 16;
    const uint32_t xmA = (uint32_t)((rA & 7) << 4);
    // B: n-row within warp N-block
    const int nrb = 64 * wn + (lane & 7) + ((lane >> 4) & 1) * 8;
    const int kaddB = ((lane >> 3) & 1) * 16;
    const uint32_t xmB = (uint32_t)((nrb & 7) << 4);

    int acch[2][8][4];
    int accl[2][8][4];
    #pragma unroll
    for (int a = 0; a < 2; ++a)
        #pragma unroll
        for (int b = 0; b < 8; ++b)
            #pragma unroll
            for (int c = 0; c < 4; ++c) { acch[a][b][c] = 0; accl[a][b][c] = 0; }

    // ---- stage loader ----
    auto load_stage = [&](int stg, int c) {
        const uint32_t st = sbase + (uint32_t)stg * STAGE_BYTES;
        const size_t ko = (size_t)c * KC;
        #pragma unroll
        for (int i = 0; i < 4; ++i) {
            const int g = tid + i * 256;
            const int row = g >> 3;
            const int col = (g & 7) << 4;
            const uint32_t soff = (uint32_t)(row * 128) + ((uint32_t)col ^ (uint32_t)((row & 7) << 4));
            const size_t goff = (size_t)row * KDIM + ko + col;
            CP16(st + soff,              pAh + goff);
            CP16(st + A_TILE + soff,     pAl + goff);
            CP16(st + 2 * A_TILE + soff, pB + goff);
        }
    };

    // ---- prologue: stages 0..2 ----
    #pragma unroll
    for (int c = 0; c < STAGES - 1; ++c) {
        load_stage(c, c);
        CP_COMMIT();
    }

    // ---- mainloop ----
    for (int c = 0; c < NCHUNK; ++c) {
        CP_WAIT(2);
        __syncthreads();
        if (c + STAGES - 1 < NCHUNK) load_stage((c + STAGES - 1) & (STAGES - 1), c + STAGES - 1);
        CP_COMMIT();

        const uint32_t st = sbase + (uint32_t)(c & (STAGES - 1)) * STAGE_BYTES;
        const uint32_t aA0 = st + (uint32_t)(rA * 128);
        const uint32_t aA1 = st + (uint32_t)((rA + 16) * 128);
        const uint32_t aB  = st + 2 * A_TILE + (uint32_t)(nrb * 128);

        #pragma unroll
        for (int ks = 0; ks < 4; ++ks) {
            const uint32_t kAh = ((uint32_t)(ks * 32 + kaddA)) ^ xmA;
            const uint32_t kB  = ((uint32_t)(ks * 32 + kaddB)) ^ xmB;
            uint32_t ah0[4], ah1[4], al0[4], al1[4];
            uint32_t bf[4][4];
            LDSM4(ah0[0], ah0[1], ah0[2], ah0[3], aA0 + kAh);
            LDSM4(ah1[0], ah1[1], ah1[2], ah1[3], aA1 + kAh);
            LDSM4(al0[0], al0[1], al0[2], al0[3], aA0 + A_TILE + kAh);
            LDSM4(al1[0], al1[1], al1[2], al1[3], aA1 + A_TILE + kAh);
            #pragma unroll
            for (int p = 0; p < 4; ++p)
                LDSM4(bf[p][0], bf[p][1], bf[p][2], bf[p][3], aB + (uint32_t)(p * 16 * 128) + kB);

            // all hi MMAs, then all lo MMAs (max distance between same-acc writes)
            #pragma unroll
            for (int nt = 0; nt < 8; ++nt) {
                const uint32_t b0 = bf[nt >> 1][(nt & 1) * 2];
                const uint32_t b1 = bf[nt >> 1][(nt & 1) * 2 + 1];
                MMA_S8(acch[0][nt], ah0[0], ah0[1], ah0[2], ah0[3], b0, b1);
                MMA_S8(acch[1][nt], ah1[0], ah1[1], ah1[2], ah1[3], b0, b1);
            }
            #pragma unroll
            for (int nt = 0; nt < 8; ++nt) {
                const uint32_t b0 = bf[nt >> 1][(nt & 1) * 2];
                const uint32_t b1 = bf[nt >> 1][(nt & 1) * 2 + 1];
                MMA_S8(accl[0][nt], al0[0], al0[1], al0[2], al0[3], b0, b1);
                MMA_S8(accl[1][nt], al1[0], al1[1], al1[2], al1[3], b0, b1);
            }
        }
    }

    // ---- epilogue: y = wscale[n] * (sA[m]*acc_hi + (sA[m]/254)*acc_lo) + bias[n] ----
    #pragma unroll
    for (int mt = 0; mt < 2; ++mt) {
        const int mr0 = m0 + 32 * wm + 16 * mt + (lane >> 2);
        const int mr1 = mr0 + 8;
        const float s0 = __ldg(g_sA + mr0);
        const float s1 = __ldg(g_sA + mr1);
        const float s0l = s0 * (1.0f / 254.0f);
        const float s1l = s1 * (1.0f / 254.0f);
        float* o0 = out + (size_t)mr0 * NDIM + n0 + 64 * wn + 2 * (lane & 3);
        float* o1 = out + (size_t)mr1 * NDIM + n0 + 64 * wn + 2 * (lane & 3);
        const float* scn = scale + n0 + 64 * wn + 2 * (lane & 3);
        const float* bin = bias + n0 + 64 * wn + 2 * (lane & 3);
        #pragma unroll
        for (int nt = 0; nt < 8; ++nt) {
            const float2 ws = *(const float2*)(scn + 8 * nt);
            const float2 bb = *(const float2*)(bin + 8 * nt);
            float2 v0, v1;
            v0.x = ws.x * (s0 * (float)acch[mt][nt][0] + s0l * (float)accl[mt][nt][0]) + bb.x;
            v0.y = ws.y * (s0 * (float)acch[mt][nt][1] + s0l * (float)accl[mt][nt][1]) + bb.y;
            v1.x = ws.x * (s1 * (float)acch[mt][nt][2] + s1l * (float)accl[mt][nt][2]) + bb.x;
            v1.y = ws.y * (s1 * (float)acch[mt][nt][3] + s1l * (float)accl[mt][nt][3]) + bb.y;
            *(float2*)(o0 + 8 * nt) = v0;
            *(float2*)(o1 + 8 * nt) = v1;
        }
    }
}

// ---------------- launcher ----------------
extern "C" void kernel_launch(void* const* d_in, const int* in_sizes, int n_in,
                              void* d_out, int out_size) {
    const float* x     = (const float*)d_in[0];
    const int*   w     = (const int*)d_in[1];
    const float* scale = (const float*)d_in[2];
    const float* bias  = (const float*)d_in[3];
    float* out = (float*)d_out;

    cudaFuncSetAttribute(qgemm_kernel, cudaFuncAttributeMaxDynamicSharedMemorySize, SMEM_BYTES);

    quant_x_kernel<<<MDIM, 128>>>(x);
    cvt_w_kernel<<<2048, 256>>>(w);

    dim3 grid(NDIM / NT, MDIM / MT);   // (32, 64) = 2048 CTAs
    qgemm_kernel<<<grid, 256, SMEM_BYTES>>>(scale, bias, out);
}

// round 4
// speedup vs baseline: 5.4115x; 5.4115x over previous
#include <cuda_runtime.h>
#include <cuda_fp16.h>
#include <cstdint>
#include <cstddef>

// ---------------- problem sizes ----------------
#define MDIM 8192
#define NDIM 4096
#define KDIM 4096
#define MT 128          // CTA tile M
#define NT 256          // CTA tile N
#define KC 64           // K elements per chunk (fp16 -> 128B rows)
#define NCHUNK (KDIM / KC)          // 64
#define STAGES 4
#define A_TILE 16384                // 128 rows x 128B
#define B_TILE 32768                // 256 rows x 128B
#define STAGE_BYTES (A_TILE + B_TILE)       // 49152
#define SMEM_BYTES (STAGES * STAGE_BYTES)   // 196608

// ---------------- device scratch (no allocation allowed) ----------------
__device__ __align__(128) __half g_X[(size_t)MDIM * KDIM];
__device__ __align__(128) __half g_W[(size_t)NDIM * KDIM];

// ---------------- PTX helpers (base sm_103 target only) -------------------
static __device__ __forceinline__ uint32_t smem_u32(const void* p) {
    uint32_t a;
    asm("{ .reg .u64 t; cvta.to.shared.u64 t, %1; cvt.u32.u64 %0, t; }" : "=r"(a) : "l"(p));
    return a;
}

#define CP16(dst, src) \
    asm volatile("cp.async.cg.shared.global [%0], [%1], 16;" :: "r"((uint32_t)(dst)), "l"(src) : "memory")
#define CP_COMMIT() asm volatile("cp.async.commit_group;" ::: "memory")
#define CP_WAIT(n)  asm volatile("cp.async.wait_group %0;" :: "n"(n) : "memory")

#define LDSM4(r0, r1, r2, r3, addr) \
    asm volatile("ldmatrix.sync.aligned.m8n8.x4.shared.b16 {%0,%1,%2,%3}, [%4];" \
                 : "=r"(r0), "=r"(r1), "=r"(r2), "=r"(r3) : "r"(addr))

// f16 MMA, fp32 accumulate: D[16x8] += A[16x16] * B[16x8]
#define MMA_F16(d, a0, a1, a2, a3, b0, b1) \
    asm volatile("mma.sync.aligned.m16n8k16.row.col.f32.f16.f16.f32 " \
                 "{%0,%1,%2,%3}, {%4,%5,%6,%7}, {%8,%9}, {%0,%1,%2,%3};" \
                 : "+f"((d)[0]), "+f"((d)[1]), "+f"((d)[2]), "+f"((d)[3]) \
                 : "r"(a0), "r"(a1), "r"(a2), "r"(a3), "r"(b0), "r"(b1))

// ---------------- prepass 1: fp32 x -> fp16 (rel err <= 2^-12) ------------
__global__ void __launch_bounds__(256) cvt_x_kernel(const float* __restrict__ x) {
    const size_t n4 = (size_t)MDIM * KDIM / 4;
    const float4* __restrict__ x4 = (const float4*)x;
    uint2* __restrict__ dst = (uint2*)g_X;
    size_t stride = (size_t)gridDim.x * blockDim.x;
    for (size_t i = (size_t)blockIdx.x * blockDim.x + threadIdx.x; i < n4; i += stride) {
        float4 v = x4[i];
        uint32_t h0 = __half_as_ushort(__float2half_rn(v.x));
        uint32_t h1 = __half_as_ushort(__float2half_rn(v.y));
        uint32_t h2 = __half_as_ushort(__float2half_rn(v.z));
        uint32_t h3 = __half_as_ushort(__float2half_rn(v.w));
        uint2 p;
        p.x = h0 | (h1 << 16);
        p.y = h2 | (h3 << 16);
        dst[i] = p;
    }
}

// ---------------- prepass 2: int32 weights -> fp16 (exact, |w|<=127) ------
__global__ void __launch_bounds__(256) cvt_w_kernel(const int* __restrict__ w) {
    const size_t n4 = (size_t)NDIM * KDIM / 4;
    const int4* __restrict__ w4 = (const int4*)w;
    uint2* __restrict__ dst = (uint2*)g_W;
    size_t stride = (size_t)gridDim.x * blockDim.x;
    for (size_t i = (size_t)blockIdx.x * blockDim.x + threadIdx.x; i < n4; i += stride) {
        int4 v = w4[i];
        uint32_t h0 = __half_as_ushort(__int2half_rn(v.x));
        uint32_t h1 = __half_as_ushort(__int2half_rn(v.y));
        uint32_t h2 = __half_as_ushort(__int2half_rn(v.z));
        uint32_t h3 = __half_as_ushort(__int2half_rn(v.w));
        uint2 p;
        p.x = h0 | (h1 << 16);
        p.y = h2 | (h3 << 16);
        dst[i] = p;
    }
}

// ---------------- main GEMM: mma.sync f16, cp.async 4-stage pipeline ------
// 256 threads = 8 warps. CTA tile 128(M) x 256(N); warp tile 64x64.
// wm = wid&1 (2 M halves), wn = wid>>1 (4 N quarters).
__global__ void __launch_bounds__(256, 1) qgemm_kernel(
    const float* __restrict__ scale,
    const float* __restrict__ bias,
    float* __restrict__ out
) {
    extern __shared__ char smem[];
    const uint32_t sbase = smem_u32(smem);
    const int tid = threadIdx.x;
    const int m0 = blockIdx.y * MT;
    const int n0 = blockIdx.x * NT;

    const int lane = tid & 31;
    const int wid = tid >> 5;
    const int wm = wid & 1;      // M half (64 rows)
    const int wn = wid >> 1;     // N quarter (64 cols)

    // gmem byte-bases (row stride = KDIM * 2 bytes = 8192 = 1<<13)
    const char* pX = (const char*)g_X + ((size_t)m0 << 13);
    const char* pW = (const char*)g_W + ((size_t)n0 << 13);

    // ldmatrix address components (same proven pattern as the s8 kernel:
    // fragments are byte-identical between s8 k32 and f16 k16)
    const int rA = 64 * wm + (lane & 7) + ((lane >> 3) & 1) * 8;
    const int kaddA = ((lane >> 4) & 1) * 16;
    const uint32_t xmA = (uint32_t)((lane & 7) << 4);
    const int nrb = 64 * wn + (lane & 7) + ((lane >> 4) & 1) * 8;
    const int kaddB = ((lane >> 3) & 1) * 16;
    const uint32_t xmB = (uint32_t)((lane & 7) << 4);

    float acc[4][8][4];
    #pragma unroll
    for (int a = 0; a < 4; ++a)
        #pragma unroll
        for (int b = 0; b < 8; ++b)
            #pragma unroll
            for (int c = 0; c < 4; ++c) acc[a][b][c] = 0.0f;

    // ---- stage loader: A 16KB (4 granules/thread) + B 32KB (8/thread) ----
    auto load_stage = [&](int stg, int c) {
        const uint32_t st = sbase + (uint32_t)stg * STAGE_BYTES;
        const uint32_t ko = (uint32_t)c << 7;       // c * 128 bytes along K
        #pragma unroll
        for (int i = 0; i < 4; ++i) {               // A: rows 0..127
            const int g = tid + i * 256;
            const int row = g >> 3;
            const int col = (g & 7) << 4;
            const uint32_t soff = (uint32_t)(row * 128) + ((uint32_t)col ^ (uint32_t)((row & 7) << 4));
            CP16(st + soff, pX + (((size_t)row << 13) + ko + col));
        }
        #pragma unroll
        for (int i = 0; i < 8; ++i) {               // B: rows 0..255
            const int g = tid + i * 256;
            const int row = g >> 3;
            const int col = (g & 7) << 4;
            const uint32_t soff = (uint32_t)(row * 128) + ((uint32_t)col ^ (uint32_t)((row & 7) << 4));
            CP16(st + A_TILE + soff, pW + (((size_t)row << 13) + ko + col));
        }
    };

    // ---- prologue: stages 0..2 ----
    #pragma unroll
    for (int c = 0; c < STAGES - 1; ++c) {
        load_stage(c, c);
        CP_COMMIT();
    }

    // ---- mainloop ----
    for (int c = 0; c < NCHUNK; ++c) {
        CP_WAIT(2);
        __syncthreads();
        if (c + STAGES - 1 < NCHUNK) load_stage((c + STAGES - 1) & (STAGES - 1), c + STAGES - 1);
        CP_COMMIT();

        const uint32_t st = sbase + (uint32_t)(c & (STAGES - 1)) * STAGE_BYTES;
        const uint32_t aA = st + (uint32_t)(rA * 128);
        const uint32_t aB = st + A_TILE + (uint32_t)(nrb * 128);

        #pragma unroll
        for (int ks = 0; ks < 4; ++ks) {
            const uint32_t kA = ((uint32_t)(ks * 32 + kaddA)) ^ xmA;
            const uint32_t kB = ((uint32_t)(ks * 32 + kaddB)) ^ xmB;
            uint32_t af[4][4];
            uint32_t bf[4][4];
            #pragma unroll
            for (int mb = 0; mb < 4; ++mb)          // 4 x m16 blocks
                LDSM4(af[mb][0], af[mb][1], af[mb][2], af[mb][3],
                      aA + (uint32_t)(mb * 16 * 128) + kA);
            #pragma unroll
            for (int p = 0; p < 4; ++p)             // 4 x n16 blocks
                LDSM4(bf[p][0], bf[p][1], bf[p][2], bf[p][3],
                      aB + (uint32_t)(p * 16 * 128) + kB);

            #pragma unroll
            for (int mb = 0; mb < 4; ++mb) {
                #pragma unroll
                for (int nt = 0; nt < 8; ++nt) {
                    const uint32_t b0 = bf[nt >> 1][(nt & 1) * 2];
                    const uint32_t b1 = bf[nt >> 1][(nt & 1) * 2 + 1];
                    MMA_F16(acc[mb][nt], af[mb][0], af[mb][1], af[mb][2], af[mb][3], b0, b1);
                }
            }
        }
    }

    // ---- epilogue: y = scale[n] * acc + bias[n] ----
    const int ncol = n0 + 64 * wn + 2 * (lane & 3);
    const float* scn = scale + ncol;
    const float* bin = bias + ncol;
    #pragma unroll
    for (int mb = 0; mb < 4; ++mb) {
        const int mr0 = m0 + 64 * wm + 16 * mb + (lane >> 2);
        const int mr1 = mr0 + 8;
        float* o0 = out + (size_t)mr0 * NDIM + ncol;
        float* o1 = out + (size_t)mr1 * NDIM + ncol;
        #pragma unroll
        for (int nt = 0; nt < 8; ++nt) {
            const float2 ws = *(const float2*)(scn + 8 * nt);
            const float2 bb = *(const float2*)(bin + 8 * nt);
            float2 v0, v1;
            v0.x = ws.x * acc[mb][nt][0] + bb.x;
            v0.y = ws.y * acc[mb][nt][1] + bb.y;
            v1.x = ws.x * acc[mb][nt][2] + bb.x;
            v1.y = ws.y * acc[mb][nt][3] + bb.y;
            *(float2*)(o0 + 8 * nt) = v0;
            *(float2*)(o1 + 8 * nt) = v1;
        }
    }
}

// ---------------- launcher ----------------
extern "C" void kernel_launch(void* const* d_in, const int* in_sizes, int n_in,
                              void* d_out, int out_size) {
    const float* x     = (const float*)d_in[0];
    const int*   w     = (const int*)d_in[1];
    const float* scale = (const float*)d_in[2];
    const float* bias  = (const float*)d_in[3];
    float* out = (float*)d_out;

    cudaFuncSetAttribute(qgemm_kernel, cudaFuncAttributeMaxDynamicSharedMemorySize, SMEM_BYTES);

    cvt_x_kernel<<<4096, 256>>>(x);
    cvt_w_kernel<<<2048, 256>>>(w);

    dim3 grid(NDIM / NT, MDIM / MT);   // (16, 64) = 1024 CTAs
    qgemm_kernel<<<grid, 256, SMEM_BYTES>>>(scale, bias, out);
}

// round 5
// speedup vs baseline: 5.4125x; 1.0002x over previous
#include <cuda_runtime.h>
#include <cuda_fp16.h>
#include <cstdint>
#include <cstddef>

// ---------------- problem sizes ----------------
#define MDIM 8192
#define NDIM 4096
#define KDIM 4096
#define MT 128          // CTA tile M
#define NT 256          // CTA tile N
#define KC 64           // K elements per chunk (fp16 -> 128B rows)
#define NCHUNK (KDIM / KC)          // 64
#define STAGES 4
#define A_TILE 16384                // 128 rows x 128B
#define B_TILE 32768                // 256 rows x 128B
#define STAGE_BYTES (A_TILE + B_TILE)       // 49152
#define SMEM_BYTES (STAGES * STAGE_BYTES)   // 196608

// ---------------- device scratch (no allocation allowed) ----------------
__device__ __align__(128) __half g_X[(size_t)MDIM * KDIM];
__device__ __align__(128) __half g_W[(size_t)NDIM * KDIM];

// ---------------- PTX helpers (base sm_103 target only) -------------------
static __device__ __forceinline__ uint32_t smem_u32(const void* p) {
    uint32_t a;
    asm("{ .reg .u64 t; cvta.to.shared.u64 t, %1; cvt.u32.u64 %0, t; }" : "=r"(a) : "l"(p));
    return a;
}

#define CP16(dst, src) \
    asm volatile("cp.async.cg.shared.global [%0], [%1], 16;" :: "r"((uint32_t)(dst)), "l"(src) : "memory")
#define CP_COMMIT() asm volatile("cp.async.commit_group;" ::: "memory")
#define CP_WAIT(n)  asm volatile("cp.async.wait_group %0;" :: "n"(n) : "memory")

#define LDSM4(r0, r1, r2, r3, addr) \
    asm volatile("ldmatrix.sync.aligned.m8n8.x4.shared.b16 {%0,%1,%2,%3}, [%4];" \
                 : "=r"(r0), "=r"(r1), "=r"(r2), "=r"(r3) : "r"(addr))

// f16 MMA, fp32 accumulate: D[16x8] += A[16x16] * B[16x8]
#define MMA_F16(d, a0, a1, a2, a3, b0, b1) \
    asm volatile("mma.sync.aligned.m16n8k16.row.col.f32.f16.f16.f32 " \
                 "{%0,%1,%2,%3}, {%4,%5,%6,%7}, {%8,%9}, {%0,%1,%2,%3};" \
                 : "+f"((d)[0]), "+f"((d)[1]), "+f"((d)[2]), "+f"((d)[3]) \
                 : "r"(a0), "r"(a1), "r"(a2), "r"(a3), "r"(b0), "r"(b1))

// ---------------- prepass 1: fp32 x -> fp16 (rel err <= 2^-12) ------------
__global__ void __launch_bounds__(256) cvt_x_kernel(const float* __restrict__ x) {
    const size_t n4 = (size_t)MDIM * KDIM / 4;
    const float4* __restrict__ x4 = (const float4*)x;
    uint2* __restrict__ dst = (uint2*)g_X;
    size_t stride = (size_t)gridDim.x * blockDim.x;
    for (size_t i = (size_t)blockIdx.x * blockDim.x + threadIdx.x; i < n4; i += stride) {
        float4 v = x4[i];
        uint32_t h0 = __half_as_ushort(__float2half_rn(v.x));
        uint32_t h1 = __half_as_ushort(__float2half_rn(v.y));
        uint32_t h2 = __half_as_ushort(__float2half_rn(v.z));
        uint32_t h3 = __half_as_ushort(__float2half_rn(v.w));
        uint2 p;
        p.x = h0 | (h1 << 16);
        p.y = h2 | (h3 << 16);
        dst[i] = p;
    }
}

// ---------------- prepass 2: int32 weights -> fp16 (exact, |w|<=127) ------
__global__ void __launch_bounds__(256) cvt_w_kernel(const int* __restrict__ w) {
    const size_t n4 = (size_t)NDIM * KDIM / 4;
    const int4* __restrict__ w4 = (const int4*)w;
    uint2* __restrict__ dst = (uint2*)g_W;
    size_t stride = (size_t)gridDim.x * blockDim.x;
    for (size_t i = (size_t)blockIdx.x * blockDim.x + threadIdx.x; i < n4; i += stride) {
        int4 v = w4[i];
        uint32_t h0 = __half_as_ushort(__int2half_rn(v.x));
        uint32_t h1 = __half_as_ushort(__int2half_rn(v.y));
        uint32_t h2 = __half_as_ushort(__int2half_rn(v.z));
        uint32_t h3 = __half_as_ushort(__int2half_rn(v.w));
        uint2 p;
        p.x = h0 | (h1 << 16);
        p.y = h2 | (h3 << 16);
        dst[i] = p;
    }
}

// ---------------- main GEMM: mma.sync f16, cp.async 4-stage pipeline ------
// 256 threads = 8 warps. CTA tile 128(M) x 256(N); warp tile 64x64.
// Fragment loads are double-buffered: ldmatrix for k-step ks+1 issues before
// the 32 MMAs of k-step ks, so LDS latency is hidden under MMA throughput.
__global__ void __launch_bounds__(256, 1) qgemm_kernel(
    const float* __restrict__ scale,
    const float* __restrict__ bias,
    float* __restrict__ out
) {
    extern __shared__ char smem[];
    const uint32_t sbase = smem_u32(smem);
    const int tid = threadIdx.x;
    const int m0 = blockIdx.y * MT;
    const int n0 = blockIdx.x * NT;

    const int lane = tid & 31;
    const int wid = tid >> 5;
    const int wm = wid & 1;      // M half (64 rows)
    const int wn = wid >> 1;     // N quarter (64 cols)

    // gmem byte-bases (row stride = KDIM * 2 bytes = 8192 = 1<<13)
    const char* pX = (const char*)g_X + ((size_t)m0 << 13);
    const char* pW = (const char*)g_W + ((size_t)n0 << 13);

    // ldmatrix address components
    const int rA = 64 * wm + (lane & 7) + ((lane >> 3) & 1) * 8;
    const int kaddA = ((lane >> 4) & 1) * 16;
    const uint32_t xmA = (uint32_t)((lane & 7) << 4);
    const int nrb = 64 * wn + (lane & 7) + ((lane >> 4) & 1) * 8;
    const int kaddB = ((lane >> 3) & 1) * 16;
    const uint32_t xmB = (uint32_t)((lane & 7) << 4);

    float acc[4][8][4];
    #pragma unroll
    for (int a = 0; a < 4; ++a)
        #pragma unroll
        for (int b = 0; b < 8; ++b)
            #pragma unroll
            for (int c = 0; c < 4; ++c) acc[a][b][c] = 0.0f;

    // double-buffered fragments
    uint32_t af[2][4][4];
    uint32_t bf[2][4][4];

    // ---- stage loader: A 16KB (4 granules/thread) + B 32KB (8/thread) ----
    auto load_stage = [&](int stg, int c) {
        const uint32_t st = sbase + (uint32_t)stg * STAGE_BYTES;
        const uint32_t ko = (uint32_t)c << 7;       // c * 128 bytes along K
        #pragma unroll
        for (int i = 0; i < 4; ++i) {               // A: rows 0..127
            const int g = tid + i * 256;
            const int row = g >> 3;
            const int col = (g & 7) << 4;
            const uint32_t soff = (uint32_t)(row * 128) + ((uint32_t)col ^ (uint32_t)((row & 7) << 4));
            CP16(st + soff, pX + (((size_t)row << 13) + ko + col));
        }
        #pragma unroll
        for (int i = 0; i < 8; ++i) {               // B: rows 0..255
            const int g = tid + i * 256;
            const int row = g >> 3;
            const int col = (g & 7) << 4;
            const uint32_t soff = (uint32_t)(row * 128) + ((uint32_t)col ^ (uint32_t)((row & 7) << 4));
            CP16(st + A_TILE + soff, pW + (((size_t)row << 13) + ko + col));
        }
    };

    // fragment loader for one k-step into buffer `buf`
    auto load_frags = [&](uint32_t aA, uint32_t aB, int ks, int buf) {
        const uint32_t kA = ((uint32_t)(ks * 32 + kaddA)) ^ xmA;
        const uint32_t kB = ((uint32_t)(ks * 32 + kaddB)) ^ xmB;
        #pragma unroll
        for (int mb = 0; mb < 4; ++mb)
            LDSM4(af[buf][mb][0], af[buf][mb][1], af[buf][mb][2], af[buf][mb][3],
                  aA + (uint32_t)(mb * 16 * 128) + kA);
        #pragma unroll
        for (int p = 0; p < 4; ++p)
            LDSM4(bf[buf][p][0], bf[buf][p][1], bf[buf][p][2], bf[buf][p][3],
                  aB + (uint32_t)(p * 16 * 128) + kB);
    };

    // ---- prologue: stages 0..2 ----
    #pragma unroll
    for (int c = 0; c < STAGES - 1; ++c) {
        load_stage(c, c);
        CP_COMMIT();
    }

    // ---- mainloop ----
    for (int c = 0; c < NCHUNK; ++c) {
        CP_WAIT(2);
        __syncthreads();
        if (c + STAGES - 1 < NCHUNK) load_stage((c + STAGES - 1) & (STAGES - 1), c + STAGES - 1);
        CP_COMMIT();

        const uint32_t st = sbase + (uint32_t)(c & (STAGES - 1)) * STAGE_BYTES;
        const uint32_t aA = st + (uint32_t)(rA * 128);
        const uint32_t aB = st + A_TILE + (uint32_t)(nrb * 128);

        load_frags(aA, aB, 0, 0);

        #pragma unroll
        for (int ks = 0; ks < 4; ++ks) {
            if (ks < 3) load_frags(aA, aB, ks + 1, (ks + 1) & 1);
            const int buf = ks & 1;
            #pragma unroll
            for (int mb = 0; mb < 4; ++mb) {
                #pragma unroll
                for (int nt = 0; nt < 8; ++nt) {
                    const uint32_t b0 = bf[buf][nt >> 1][(nt & 1) * 2];
                    const uint32_t b1 = bf[buf][nt >> 1][(nt & 1) * 2 + 1];
                    MMA_F16(acc[mb][nt],
                            af[buf][mb][0], af[buf][mb][1], af[buf][mb][2], af[buf][mb][3],
                            b0, b1);
                }
            }
        }
    }

    // ---- epilogue: y = scale[n] * acc + bias[n] ----
    const int ncol = n0 + 64 * wn + 2 * (lane & 3);
    const float* scn = scale + ncol;
    const float* bin = bias + ncol;
    #pragma unroll
    for (int mb = 0; mb < 4; ++mb) {
        const int mr0 = m0 + 64 * wm + 16 * mb + (lane >> 2);
        const int mr1 = mr0 + 8;
        float* o0 = out + (size_t)mr0 * NDIM + ncol;
        float* o1 = out + (size_t)mr1 * NDIM + ncol;
        #pragma unroll
        for (int nt = 0; nt < 8; ++nt) {
            const float2 ws = *(const float2*)(scn + 8 * nt);
            const float2 bb = *(const float2*)(bin + 8 * nt);
            float2 v0, v1;
            v0.x = ws.x * acc[mb][nt][0] + bb.x;
            v0.y = ws.y * acc[mb][nt][1] + bb.y;
            v1.x = ws.x * acc[mb][nt][2] + bb.x;
            v1.y = ws.y * acc[mb][nt][3] + bb.y;
            *(float2*)(o0 + 8 * nt) = v0;
            *(float2*)(o1 + 8 * nt) = v1;
        }
    }
}

// ---------------- launcher ----------------
extern "C" void kernel_launch(void* const* d_in, const int* in_sizes, int n_in,
                              void* d_out, int out_size) {
    const float* x     = (const float*)d_in[0];
    const int*   w     = (const int*)d_in[1];
    const float* scale = (const float*)d_in[2];
    const float* bias  = (const float*)d_in[3];
    float* out = (float*)d_out;

    cudaFuncSetAttribute(qgemm_kernel, cudaFuncAttributeMaxDynamicSharedMemorySize, SMEM_BYTES);

    cvt_x_kernel<<<4096, 256>>>(x);
    cvt_w_kernel<<<2048, 256>>>(w);

    dim3 grid(NDIM / NT, MDIM / MT);   // (16, 64) = 1024 CTAs
    qgemm_kernel<<<grid, 256, SMEM_BYTES>>>(scale, bias, out);
}